// round 1
// baseline (speedup 1.0000x reference)
#include <cuda_runtime.h>
#include <math.h>

#define Bx 2
#define Lx 2048
#define Cx 1024
#define Hx 16
#define Dx 64
#define MTOT (Bx*Lx)          // 4096

// Scratch (allocation-free rule: __device__ globals)
__device__ float g_qkv[MTOT * 3 * Cx];                      // 50 MB
__device__ float g_scores[(size_t)Bx * Hx * Lx * Lx];       // 512 MB
__device__ float g_attn[MTOT * Cx];                         // 16 MB

// ---------------------------------------------------------------------------
// Core 128x128x8 SGEMM with bias epilogue. 256 threads, 8x8 microtile.
// A: [M,K] row-major, Bw: [K,N] row-major, C = A@Bw + bias[n].
// Requires M%128==0, N%128==0, K%8==0, and 16B-aligned rows (K%4==0, N%4==0).
// ---------------------------------------------------------------------------
__device__ __forceinline__ void sgemm_core(const float* __restrict__ A,
                                           const float* __restrict__ Bw,
                                           const float* __restrict__ bias,
                                           float* __restrict__ Cc,
                                           int M, int N, int K)
{
    __shared__ float As[8][128];
    __shared__ float Bs[8][128];

    const int tid = threadIdx.x;
    const int m0 = blockIdx.y * 128;
    const int n0 = blockIdx.x * 128;
    const int tr = tid >> 4;   // 0..15 -> rows tr*8..tr*8+7
    const int tc = tid & 15;   // 0..15 -> cols tc*8..tc*8+7

    float acc[8][8];
    #pragma unroll
    for (int i = 0; i < 8; ++i)
        #pragma unroll
        for (int j = 0; j < 8; ++j) acc[i][j] = 0.f;

    const int arow = tid >> 1;
    const int akc  = (tid & 1) * 4;
    const int brow = tid >> 5;
    const int bcol = (tid & 31) * 4;

    for (int k0 = 0; k0 < K; k0 += 8) {
        // A tile 128x8 -> transposed into As[k][m]
        float4 a4 = *reinterpret_cast<const float4*>(&A[(size_t)(m0 + arow) * K + k0 + akc]);
        As[akc + 0][arow] = a4.x;
        As[akc + 1][arow] = a4.y;
        As[akc + 2][arow] = a4.z;
        As[akc + 3][arow] = a4.w;
        // B tile 8x128
        *reinterpret_cast<float4*>(&Bs[brow][bcol]) =
            *reinterpret_cast<const float4*>(&Bw[(size_t)(k0 + brow) * N + n0 + bcol]);
        __syncthreads();

        #pragma unroll
        for (int k = 0; k < 8; ++k) {
            float a[8], b[8];
            #pragma unroll
            for (int i = 0; i < 8; ++i) a[i] = As[k][tr * 8 + i];
            #pragma unroll
            for (int j = 0; j < 8; ++j) b[j] = Bs[k][tc * 8 + j];
            #pragma unroll
            for (int i = 0; i < 8; ++i)
                #pragma unroll
                for (int j = 0; j < 8; ++j)
                    acc[i][j] += a[i] * b[j];
        }
        __syncthreads();
    }

    #pragma unroll
    for (int i = 0; i < 8; ++i) {
        const int m = m0 + tr * 8 + i;
        float* crow = &Cc[(size_t)m * N + n0 + tc * 8];
        #pragma unroll
        for (int j = 0; j < 8; ++j) crow[j] = acc[i][j] + bias[n0 + tc * 8 + j];
    }
}

__global__ void qkv_gemm_kernel(const float* __restrict__ x,
                                const float* __restrict__ W,
                                const float* __restrict__ bias)
{
    sgemm_core(x, W, bias, g_qkv, MTOT, 3 * Cx, Cx);
}

__global__ void out_gemm_kernel(const float* __restrict__ W,
                                const float* __restrict__ bias,
                                float* __restrict__ out)
{
    sgemm_core(g_attn, W, bias, out, MTOT, Cx, Cx);
}

// ---------------------------------------------------------------------------
// RMS norm (sqrt(sum x^2), eps clamp, *gamma*sqrt(D)) + interleaved RoPE,
// applied in place to q and k inside g_qkv. One warp per (token, head).
// ---------------------------------------------------------------------------
__global__ void norm_rope_kernel(const float* __restrict__ cosv,
                                 const float* __restrict__ sinv,
                                 const float* __restrict__ gq,
                                 const float* __restrict__ gk)
{
    const int warp = (blockIdx.x * blockDim.x + threadIdx.x) >> 5;
    const int lane = threadIdx.x & 31;
    const int m = warp >> 4;      // token index 0..4095 (= b*L + l)
    const int h = warp & 15;

    const float c = cosv[m * 32 + lane];
    const float s = sinv[m * 32 + lane];

    #pragma unroll
    for (int part = 0; part < 2; ++part) {
        float* ptr = &g_qkv[(size_t)m * 3072 + part * 1024 + h * 64];
        const float* gamma = (part == 0) ? gq : gk;
        float2 v = *reinterpret_cast<float2*>(ptr + 2 * lane);
        float ss = v.x * v.x + v.y * v.y;
        #pragma unroll
        for (int o = 16; o; o >>= 1) ss += __shfl_xor_sync(0xffffffffu, ss, o);
        const float norm = sqrtf(ss);
        const float inv = 8.0f / fmaxf(norm, 1e-12f);   // sqrt(D)=8
        const float re = v.x * inv * gamma[h * 64 + 2 * lane];
        const float im = v.y * inv * gamma[h * 64 + 2 * lane + 1];
        float2 o2;
        o2.x = re * c - im * s;
        o2.y = re * s + im * c;
        *reinterpret_cast<float2*>(ptr + 2 * lane) = o2;
    }
}

// ---------------------------------------------------------------------------
// Scores: S[b,h,l,m] = (q . k) / 8. Per block: one (b,h), 64x64 output tile,
// full K=64 in shared. 256 threads, 4x4 microtile.
// ---------------------------------------------------------------------------
__global__ void qk_scores_kernel()
{
    __shared__ float Qs[64][65];
    __shared__ float Ks[64][65];

    const int bh = blockIdx.z;            // 0..31
    const int b = bh >> 4, h = bh & 15;
    const int l0 = blockIdx.y * 64;
    const int m0 = blockIdx.x * 64;
    const int tid = threadIdx.x;

    const float* qbase = &g_qkv[(size_t)(b * Lx + l0) * 3072 + h * 64];
    const float* kbase = &g_qkv[(size_t)(b * Lx + m0) * 3072 + 1024 + h * 64];

    #pragma unroll
    for (int i = 0; i < 4; ++i) {
        const int e = tid + i * 256;
        const int row = e >> 4;
        const int c4 = (e & 15) * 4;
        float4 q4 = *reinterpret_cast<const float4*>(qbase + (size_t)row * 3072 + c4);
        Qs[row][c4 + 0] = q4.x; Qs[row][c4 + 1] = q4.y;
        Qs[row][c4 + 2] = q4.z; Qs[row][c4 + 3] = q4.w;
        float4 k4 = *reinterpret_cast<const float4*>(kbase + (size_t)row * 3072 + c4);
        Ks[row][c4 + 0] = k4.x; Ks[row][c4 + 1] = k4.y;
        Ks[row][c4 + 2] = k4.z; Ks[row][c4 + 3] = k4.w;
    }
    __syncthreads();

    const int tr = tid >> 4;   // 0..15 -> 4 rows
    const int tc = tid & 15;   // 0..15 -> 4 cols
    float acc[4][4];
    #pragma unroll
    for (int i = 0; i < 4; ++i)
        #pragma unroll
        for (int j = 0; j < 4; ++j) acc[i][j] = 0.f;

    #pragma unroll 8
    for (int d = 0; d < 64; ++d) {
        float a[4], bb[4];
        #pragma unroll
        for (int i = 0; i < 4; ++i) a[i] = Qs[tr * 4 + i][d];
        #pragma unroll
        for (int j = 0; j < 4; ++j) bb[j] = Ks[tc * 4 + j][d];
        #pragma unroll
        for (int i = 0; i < 4; ++i)
            #pragma unroll
            for (int j = 0; j < 4; ++j)
                acc[i][j] += a[i] * bb[j];
    }

    const float scale = 0.125f;   // 1/sqrt(64)
    #pragma unroll
    for (int i = 0; i < 4; ++i) {
        const size_t row = (size_t)bh * Lx + (l0 + tr * 4 + i);
        float4 o;
        o.x = acc[i][0] * scale; o.y = acc[i][1] * scale;
        o.z = acc[i][2] * scale; o.w = acc[i][3] * scale;
        *reinterpret_cast<float4*>(&g_scores[row * Lx + m0 + tc * 4]) = o;
    }
}

// ---------------------------------------------------------------------------
// Softmax over rows of length 2048. One warp per row, values in registers.
// ---------------------------------------------------------------------------
__global__ void softmax_kernel()
{
    const int warp = (blockIdx.x * blockDim.x + threadIdx.x) >> 5;
    const int lane = threadIdx.x & 31;
    float* row = &g_scores[(size_t)warp * Lx];

    float4 v[16];
    float mx = -1e30f;
    #pragma unroll
    for (int j = 0; j < 16; ++j) {
        v[j] = *reinterpret_cast<float4*>(row + j * 128 + lane * 4);
        mx = fmaxf(mx, fmaxf(fmaxf(v[j].x, v[j].y), fmaxf(v[j].z, v[j].w)));
    }
    #pragma unroll
    for (int o = 16; o; o >>= 1) mx = fmaxf(mx, __shfl_xor_sync(0xffffffffu, mx, o));

    float sum = 0.f;
    #pragma unroll
    for (int j = 0; j < 16; ++j) {
        v[j].x = __expf(v[j].x - mx);
        v[j].y = __expf(v[j].y - mx);
        v[j].z = __expf(v[j].z - mx);
        v[j].w = __expf(v[j].w - mx);
        sum += (v[j].x + v[j].y) + (v[j].z + v[j].w);
    }
    #pragma unroll
    for (int o = 16; o; o >>= 1) sum += __shfl_xor_sync(0xffffffffu, sum, o);
    const float inv = 1.0f / sum;

    #pragma unroll
    for (int j = 0; j < 16; ++j) {
        v[j].x *= inv; v[j].y *= inv; v[j].z *= inv; v[j].w *= inv;
        *reinterpret_cast<float4*>(row + j * 128 + lane * 4) = v[j];
    }
}

// ---------------------------------------------------------------------------
// PV: O[b,l,h,:] = probs[b,h,l,:] @ V[b,:,h,:]. Per block: one (b,h),
// 128 rows x 64 cols (full D), K-chunks of 32. 256 threads, 8x4 microtile.
// ---------------------------------------------------------------------------
__global__ void pv_kernel()
{
    __shared__ float Ps[128][33];
    __shared__ float Vs[32][65];

    const int bh = blockIdx.y;           // 0..31
    const int b = bh >> 4, h = bh & 15;
    const int l0 = blockIdx.x * 128;
    const int tid = threadIdx.x;
    const int tr = tid >> 4;   // 0..15 -> 8 rows
    const int tc = tid & 15;   // 0..15 -> 4 cols

    float acc[8][4];
    #pragma unroll
    for (int i = 0; i < 8; ++i)
        #pragma unroll
        for (int j = 0; j < 4; ++j) acc[i][j] = 0.f;

    const float* prow = &g_scores[((size_t)bh * Lx + l0) * Lx];
    const float* vbase = &g_qkv[(size_t)b * Lx * 3072 + 2048 + h * 64];

    for (int kt = 0; kt < Lx; kt += 32) {
        // Ps: 128 x 32
        #pragma unroll
        for (int i = 0; i < 4; ++i) {
            const int e = tid + i * 256;
            const int row = e >> 3;
            const int c4 = (e & 7) * 4;
            float4 p4 = *reinterpret_cast<const float4*>(prow + (size_t)row * Lx + kt + c4);
            Ps[row][c4 + 0] = p4.x; Ps[row][c4 + 1] = p4.y;
            Ps[row][c4 + 2] = p4.z; Ps[row][c4 + 3] = p4.w;
        }
        // Vs: 32 x 64
        #pragma unroll
        for (int i = 0; i < 2; ++i) {
            const int e = tid + i * 256;
            const int row = e >> 4;
            const int c4 = (e & 15) * 4;
            float4 v4 = *reinterpret_cast<const float4*>(vbase + (size_t)(kt + row) * 3072 + c4);
            Vs[row][c4 + 0] = v4.x; Vs[row][c4 + 1] = v4.y;
            Vs[row][c4 + 2] = v4.z; Vs[row][c4 + 3] = v4.w;
        }
        __syncthreads();

        #pragma unroll 8
        for (int k = 0; k < 32; ++k) {
            float a[8], bb[4];
            #pragma unroll
            for (int i = 0; i < 8; ++i) a[i] = Ps[tr * 8 + i][k];
            #pragma unroll
            for (int j = 0; j < 4; ++j) bb[j] = Vs[k][tc * 4 + j];
            #pragma unroll
            for (int i = 0; i < 8; ++i)
                #pragma unroll
                for (int j = 0; j < 4; ++j)
                    acc[i][j] += a[i] * bb[j];
        }
        __syncthreads();
    }

    #pragma unroll
    for (int i = 0; i < 8; ++i) {
        const size_t m = (size_t)b * Lx + l0 + tr * 8 + i;
        float4 o;
        o.x = acc[i][0]; o.y = acc[i][1]; o.z = acc[i][2]; o.w = acc[i][3];
        *reinterpret_cast<float4*>(&g_attn[m * Cx + h * 64 + tc * 4]) = o;
    }
}

// ---------------------------------------------------------------------------
extern "C" void kernel_launch(void* const* d_in, const int* in_sizes, int n_in,
                              void* d_out, int out_size)
{
    const float* x    = (const float*)d_in[0];
    const float* pcos = (const float*)d_in[1];
    const float* psin = (const float*)d_in[2];
    const float* Wqkv = (const float*)d_in[3];
    const float* bqkv = (const float*)d_in[4];
    const float* gq   = (const float*)d_in[5];
    const float* gk   = (const float*)d_in[6];
    const float* Wout = (const float*)d_in[7];
    const float* bout = (const float*)d_in[8];
    float* out = (float*)d_out;

    // 1. QKV GEMM + bias -> g_qkv
    qkv_gemm_kernel<<<dim3(3 * Cx / 128, MTOT / 128), 256>>>(x, Wqkv, bqkv);
    // 2. RMS norm + RoPE in place on q,k
    norm_rope_kernel<<<(MTOT * Hx) / 8, 256>>>(pcos, psin, gq, gk);
    // 3. Q K^T * scale -> g_scores
    qk_scores_kernel<<<dim3(Lx / 64, Lx / 64, Bx * Hx), 256>>>();
    // 4. Row softmax in place
    softmax_kernel<<<(Bx * Hx * Lx) / 8, 256>>>();
    // 5. P @ V -> g_attn
    pv_kernel<<<dim3(Lx / 128, Bx * Hx), 256>>>();
    // 6. Out GEMM + bias -> d_out
    out_gemm_kernel<<<dim3(Cx / 128, MTOT / 128), 256>>>(Wout, bout, out);
}

// round 9
// speedup vs baseline: 1.1722x; 1.1722x over previous
#include <cuda_runtime.h>
#include <math.h>

#define Bx 2
#define Lx 2048
#define Cx 1024
#define Hx 16
#define Dx 64
#define MTOT (Bx*Lx)          // 4096

// Scratch (subset of the passing round-1 set; g_scores eliminated by fusion)
__device__ float g_qkv[MTOT * 3 * Cx];                      // 50 MB
__device__ float g_attn[MTOT * Cx];                         // 16 MB

// ===========================================================================
// SGEMM 128x128x8-chunk with bias epilogue (round-1 core, float4 fragment
// loads to remove the 4-way b-load bank conflict). 256 threads, 8x8 microtile.
// ===========================================================================
__device__ __forceinline__ void sgemm_core(const float* __restrict__ A,
                                           const float* __restrict__ Bw,
                                           const float* __restrict__ bias,
                                           float* __restrict__ Cc,
                                           int M, int N, int K)
{
    __shared__ float As[8][128];
    __shared__ float Bs[8][128];

    const int tid = threadIdx.x;
    const int m0 = blockIdx.y * 128;
    const int n0 = blockIdx.x * 128;
    const int tr = tid >> 4;
    const int tc = tid & 15;

    float acc[8][8];
    #pragma unroll
    for (int i = 0; i < 8; ++i)
        #pragma unroll
        for (int j = 0; j < 8; ++j) acc[i][j] = 0.f;

    const int arow = tid >> 1;
    const int akc  = (tid & 1) * 4;
    const int brow = tid >> 5;
    const int bcol = (tid & 31) * 4;

    for (int k0 = 0; k0 < K; k0 += 8) {
        float4 a4 = *reinterpret_cast<const float4*>(&A[(size_t)(m0 + arow) * K + k0 + akc]);
        As[akc + 0][arow] = a4.x;
        As[akc + 1][arow] = a4.y;
        As[akc + 2][arow] = a4.z;
        As[akc + 3][arow] = a4.w;
        *reinterpret_cast<float4*>(&Bs[brow][bcol]) =
            *reinterpret_cast<const float4*>(&Bw[(size_t)(k0 + brow) * N + n0 + bcol]);
        __syncthreads();

        #pragma unroll
        for (int k = 0; k < 8; ++k) {
            float4 av0 = *reinterpret_cast<const float4*>(&As[k][tr * 8]);
            float4 av1 = *reinterpret_cast<const float4*>(&As[k][tr * 8 + 4]);
            float4 bv0 = *reinterpret_cast<const float4*>(&Bs[k][tc * 8]);
            float4 bv1 = *reinterpret_cast<const float4*>(&Bs[k][tc * 8 + 4]);
            float a[8]; float b[8];
            a[0]=av0.x; a[1]=av0.y; a[2]=av0.z; a[3]=av0.w;
            a[4]=av1.x; a[5]=av1.y; a[6]=av1.z; a[7]=av1.w;
            b[0]=bv0.x; b[1]=bv0.y; b[2]=bv0.z; b[3]=bv0.w;
            b[4]=bv1.x; b[5]=bv1.y; b[6]=bv1.z; b[7]=bv1.w;
            #pragma unroll
            for (int i = 0; i < 8; ++i)
                #pragma unroll
                for (int j = 0; j < 8; ++j)
                    acc[i][j] += a[i] * b[j];
        }
        __syncthreads();
    }

    #pragma unroll
    for (int i = 0; i < 8; ++i) {
        const int m = m0 + tr * 8 + i;
        float* crow = &Cc[(size_t)m * N + n0 + tc * 8];
        #pragma unroll
        for (int j = 0; j < 8; ++j) crow[j] = acc[i][j] + bias[n0 + tc * 8 + j];
    }
}

__global__ void qkv_gemm_kernel(const float* __restrict__ x,
                                const float* __restrict__ W,
                                const float* __restrict__ bias)
{
    sgemm_core(x, W, bias, g_qkv, MTOT, 3 * Cx, Cx);
}

__global__ void out_gemm_kernel(const float* __restrict__ W,
                                const float* __restrict__ bias,
                                float* __restrict__ out)
{
    sgemm_core(g_attn, W, bias, out, MTOT, Cx, Cx);
}

// ---------------------------------------------------------------------------
// RMS norm + RoPE (in place on q,k). One warp per (token, head). [round-1]
// ---------------------------------------------------------------------------
__global__ void norm_rope_kernel(const float* __restrict__ cosv,
                                 const float* __restrict__ sinv,
                                 const float* __restrict__ gq,
                                 const float* __restrict__ gk)
{
    const int warp = (blockIdx.x * blockDim.x + threadIdx.x) >> 5;
    const int lane = threadIdx.x & 31;
    const int m = warp >> 4;
    const int h = warp & 15;

    const float c = cosv[m * 32 + lane];
    const float s = sinv[m * 32 + lane];

    #pragma unroll
    for (int part = 0; part < 2; ++part) {
        float* ptr = &g_qkv[(size_t)m * 3072 + part * 1024 + h * 64];
        const float* gamma = (part == 0) ? gq : gk;
        float2 v = *reinterpret_cast<float2*>(ptr + 2 * lane);
        float ss = v.x * v.x + v.y * v.y;
        #pragma unroll
        for (int o = 16; o; o >>= 1) ss += __shfl_xor_sync(0xffffffffu, ss, o);
        const float inv = 8.0f / fmaxf(sqrtf(ss), 1e-12f);
        const float re = v.x * inv * gamma[h * 64 + 2 * lane];
        const float im = v.y * inv * gamma[h * 64 + 2 * lane + 1];
        float2 o2;
        o2.x = re * c - im * s;
        o2.y = re * s + im * c;
        *reinterpret_cast<float2*>(ptr + 2 * lane) = o2;
    }
}

// ===========================================================================
// Fused flash attention: per block = one (b,h) x 128 q-rows. 256 threads.
// Streams K/V in 64-key tiles; online softmax; O accumulated in registers.
// Thread (tr = tid>>4, tc = tid&15): rows tr*8..+7, S-cols tc*4..+3 (of 64),
// O-cols tc*4..+3 (of 64).
// Dynamic smem: Qs[128][68] | Ks[64][70] | Vs[64][68] | Ps[128][68]
// ===========================================================================
#define FL_QS (128 * 68)
#define FL_KS (64 * 70)
#define FL_VS (64 * 68)
#define FL_PS (128 * 68)
#define FL_SMEM_BYTES ((FL_QS + FL_KS + FL_VS + FL_PS) * 4)

__global__ void __launch_bounds__(256)
flash_attn_kernel()
{
    extern __shared__ float fsm[];
    float* Qs = fsm;
    float* Ks = fsm + FL_QS;
    float* Vs = Ks + FL_KS;
    float* Ps = Vs + FL_VS;

    const int bh = blockIdx.y;            // 0..31
    const int b = bh >> 4, h = bh & 15;
    const int l0 = blockIdx.x * 128;
    const int tid = threadIdx.x;
    const int tr = tid >> 4;
    const int tc = tid & 15;

    // Load Q tile (x 1/sqrt(D) folded here)
    #pragma unroll
    for (int i = 0; i < 8; ++i) {
        const int e = tid + i * 256;
        const int row = e >> 4, c4 = (e & 15) * 4;
        float4 q = *reinterpret_cast<const float4*>(
            &g_qkv[(size_t)(b * Lx + l0 + row) * 3072 + h * 64 + c4]);
        q.x *= 0.125f; q.y *= 0.125f; q.z *= 0.125f; q.w *= 0.125f;
        *reinterpret_cast<float4*>(&Qs[row * 68 + c4]) = q;
    }

    float o[8][4];
    float mrow[8], lrow[8];
    #pragma unroll
    for (int i = 0; i < 8; ++i) {
        mrow[i] = -3.0e38f; lrow[i] = 0.f;
        #pragma unroll
        for (int j = 0; j < 4; ++j) o[i][j] = 0.f;
    }

    for (int kb = 0; kb < Lx / 64; ++kb) {
        __syncthreads();   // prev PV done; Qs visible (first iter)
        // Load K,V tiles (64 keys x 64 dims)
        #pragma unroll
        for (int i = 0; i < 4; ++i) {
            const int e = tid + i * 256;
            const int row = e >> 4, c4 = (e & 15) * 4;
            const float* base = &g_qkv[(size_t)(b * Lx + kb * 64 + row) * 3072 + h * 64 + c4];
            float4 kv = *reinterpret_cast<const float4*>(base + 1024);
            float2 k0; k0.x = kv.x; k0.y = kv.y;
            float2 k1; k1.x = kv.z; k1.y = kv.w;
            *reinterpret_cast<float2*>(&Ks[row * 70 + c4]) = k0;
            *reinterpret_cast<float2*>(&Ks[row * 70 + c4 + 2]) = k1;
            float4 vv = *reinterpret_cast<const float4*>(base + 2048);
            *reinterpret_cast<float4*>(&Vs[row * 68 + c4]) = vv;
        }
        __syncthreads();

        // S = Q . K^T  (8x4 per thread)
        float s[8][4];
        #pragma unroll
        for (int i = 0; i < 8; ++i)
            #pragma unroll
            for (int j = 0; j < 4; ++j) s[i][j] = 0.f;

        #pragma unroll
        for (int d = 0; d < 64; d += 4) {
            float a[8][4];
            #pragma unroll
            for (int i = 0; i < 8; ++i) {
                float4 av = *reinterpret_cast<const float4*>(&Qs[(tr * 8 + i) * 68 + d]);
                a[i][0] = av.x; a[i][1] = av.y; a[i][2] = av.z; a[i][3] = av.w;
            }
            #pragma unroll
            for (int j = 0; j < 4; ++j) {
                float2 b0 = *reinterpret_cast<const float2*>(&Ks[(tc * 4 + j) * 70 + d]);
                float2 b1 = *reinterpret_cast<const float2*>(&Ks[(tc * 4 + j) * 70 + d + 2]);
                #pragma unroll
                for (int i = 0; i < 8; ++i)
                    s[i][j] += a[i][0] * b0.x + a[i][1] * b0.y
                             + a[i][2] * b1.x + a[i][3] * b1.y;
            }
        }

        // Online softmax update + write P
        #pragma unroll
        for (int i = 0; i < 8; ++i) {
            float mx = fmaxf(fmaxf(s[i][0], s[i][1]), fmaxf(s[i][2], s[i][3]));
            mx = fmaxf(mx, __shfl_xor_sync(0xffffffffu, mx, 8, 16));
            mx = fmaxf(mx, __shfl_xor_sync(0xffffffffu, mx, 4, 16));
            mx = fmaxf(mx, __shfl_xor_sync(0xffffffffu, mx, 2, 16));
            mx = fmaxf(mx, __shfl_xor_sync(0xffffffffu, mx, 1, 16));
            const float mnew = fmaxf(mrow[i], mx);
            const float alpha = __expf(mrow[i] - mnew);
            mrow[i] = mnew;
            const float p0 = __expf(s[i][0] - mnew);
            const float p1 = __expf(s[i][1] - mnew);
            const float p2 = __expf(s[i][2] - mnew);
            const float p3 = __expf(s[i][3] - mnew);
            float rs = (p0 + p1) + (p2 + p3);
            rs += __shfl_xor_sync(0xffffffffu, rs, 8, 16);
            rs += __shfl_xor_sync(0xffffffffu, rs, 4, 16);
            rs += __shfl_xor_sync(0xffffffffu, rs, 2, 16);
            rs += __shfl_xor_sync(0xffffffffu, rs, 1, 16);
            lrow[i] = lrow[i] * alpha + rs;
            o[i][0] *= alpha; o[i][1] *= alpha; o[i][2] *= alpha; o[i][3] *= alpha;
            float4 pv; pv.x = p0; pv.y = p1; pv.z = p2; pv.w = p3;
            *reinterpret_cast<float4*>(&Ps[(tr * 8 + i) * 68 + tc * 4]) = pv;
        }
        __syncthreads();

        // O += P . V  (8x4 per thread over 64 keys)
        #pragma unroll
        for (int k = 0; k < 64; k += 4) {
            float a[8][4];
            #pragma unroll
            for (int i = 0; i < 8; ++i) {
                float4 av = *reinterpret_cast<const float4*>(&Ps[(tr * 8 + i) * 68 + k]);
                a[i][0] = av.x; a[i][1] = av.y; a[i][2] = av.z; a[i][3] = av.w;
            }
            #pragma unroll
            for (int kk = 0; kk < 4; ++kk) {
                float4 bv = *reinterpret_cast<const float4*>(&Vs[(k + kk) * 68 + tc * 4]);
                #pragma unroll
                for (int i = 0; i < 8; ++i) {
                    o[i][0] += a[i][kk] * bv.x;
                    o[i][1] += a[i][kk] * bv.y;
                    o[i][2] += a[i][kk] * bv.z;
                    o[i][3] += a[i][kk] * bv.w;
                }
            }
        }
    }

    // Normalize and write O
    #pragma unroll
    for (int i = 0; i < 8; ++i) {
        const float inv = 1.0f / lrow[i];
        float4 ov;
        ov.x = o[i][0] * inv; ov.y = o[i][1] * inv;
        ov.z = o[i][2] * inv; ov.w = o[i][3] * inv;
        *reinterpret_cast<float4*>(
            &g_attn[(size_t)(b * Lx + l0 + tr * 8 + i) * 1024 + h * 64 + tc * 4]) = ov;
    }
}

// ---------------------------------------------------------------------------
extern "C" void kernel_launch(void* const* d_in, const int* in_sizes, int n_in,
                              void* d_out, int out_size)
{
    const float* x    = (const float*)d_in[0];
    const float* pcos = (const float*)d_in[1];
    const float* psin = (const float*)d_in[2];
    const float* Wqkv = (const float*)d_in[3];
    const float* bqkv = (const float*)d_in[4];
    const float* gq   = (const float*)d_in[5];
    const float* gk   = (const float*)d_in[6];
    const float* Wout = (const float*)d_in[7];
    const float* bout = (const float*)d_in[8];
    float* out = (float*)d_out;

    cudaFuncSetAttribute(flash_attn_kernel,
                         cudaFuncAttributeMaxDynamicSharedMemorySize, FL_SMEM_BYTES);

    // 1. QKV GEMM + bias -> g_qkv
    qkv_gemm_kernel<<<dim3(3 * Cx / 128, MTOT / 128), 256>>>(x, Wqkv, bqkv);
    // 2. RMS norm + RoPE in place on q,k
    norm_rope_kernel<<<(MTOT * Hx) / 8, 256>>>(pcos, psin, gq, gk);
    // 3. Fused attention (QK^T -> online softmax -> PV) -> g_attn
    flash_attn_kernel<<<dim3(Lx / 128, Bx * Hx), 256, FL_SMEM_BYTES>>>();
    // 4. Out GEMM + bias -> d_out
    out_gemm_kernel<<<dim3(Cx / 128, MTOT / 128), 256>>>(Wout, bout, out);
}